// round 3
// baseline (speedup 1.0000x reference)
#include <cuda_runtime.h>
#include <cuda_bf16.h>
#include <cstdint>

typedef unsigned int u32;

#define D        512
#define BDIM     1024
#define C        200
#define NKEYS    50000

#define BM       128
#define BN       128
#define BK       64
#define NTILES   ((NKEYS + BN - 1) / BN)   // 391
#define NPAD     (NTILES * BN)             // 50048
#define BTILES   (BDIM / BM)               // 8
#define NGROUPS  18                        // 8*18 = 144 CTAs = one wave

#define SA       72                        // padded bf16 stride for smem tiles

// ---------------- device scratch (no allocations allowed) ----------------
__device__ __nv_bfloat16 g_qbf[BDIM][D];
__device__ float         g_qf [BDIM * D];
__device__ float         g_tf [C * D];
__device__ __nv_bfloat16 g_kbf[NPAD][D];      // zero-init padding rows
__device__ int           g_lab[NPAD];
__device__ float         g_cacc[BDIM * C];

// ---------------- helpers ----------------
__device__ __forceinline__ void ldmx4(u32& r0, u32& r1, u32& r2,
                                      u32& r3, const void* p) {
    u32 addr = (u32)__cvta_generic_to_shared(p);
    asm volatile("ldmatrix.sync.aligned.m8n8.x4.shared.b16 {%0,%1,%2,%3}, [%4];\n"
                 : "=r"(r0), "=r"(r1), "=r"(r2), "=r"(r3)
                 : "r"(addr));
}

__device__ __forceinline__ void mma_bf16(float* d, const u32* a, const u32* b) {
    asm volatile(
        "mma.sync.aligned.m16n8k16.row.col.f32.bf16.bf16.f32 "
        "{%0,%1,%2,%3}, {%4,%5,%6,%7}, {%8,%9}, {%0,%1,%2,%3};\n"
        : "+f"(d[0]), "+f"(d[1]), "+f"(d[2]), "+f"(d[3])
        : "r"(a[0]), "r"(a[1]), "r"(a[2]), "r"(a[3]), "r"(b[0]), "r"(b[1]));
}

// ---------------- prep kernels ----------------
__global__ void prep_misc(const int* __restrict__ labels) {
    int i = blockIdx.x * blockDim.x + threadIdx.x;
    if (i < BDIM * C) g_cacc[i] = 0.f;
    if (i < NPAD) {
        int l = (i < NKEYS) ? labels[i] : 0;
        l = (l < 0) ? 0 : ((l >= C) ? C - 1 : l);   // clamp: never crash on dtype surprises
        g_lab[i] = l;
    }
}

// one row per block, 128 threads, D=512 -> float4 per thread
__device__ __forceinline__ float row_sumsq_inv(const float* src, float4& x) {
    int t = threadIdx.x;
    x = ((const float4*)src)[t];
    float ss = x.x * x.x + x.y * x.y + x.z * x.z + x.w * x.w;
#pragma unroll
    for (int o = 16; o; o >>= 1) ss += __shfl_xor_sync(0xffffffffu, ss, o);
    __shared__ float ws[4];
    if ((t & 31) == 0) ws[t >> 5] = ss;
    __syncthreads();
    float tot = ws[0] + ws[1] + ws[2] + ws[3];
    return rsqrtf(tot);
}

__global__ void prep_q(const float* __restrict__ img) {
    int row = blockIdx.x, t = threadIdx.x;
    float4 x;
    float inv = row_sumsq_inv(img + row * D, x);
    float4 y = make_float4(x.x * inv, x.y * inv, x.z * inv, x.w * inv);
    ((float4*)(g_qf + row * D))[t] = y;
    g_qbf[row][4 * t + 0] = __float2bfloat16(y.x);
    g_qbf[row][4 * t + 1] = __float2bfloat16(y.y);
    g_qbf[row][4 * t + 2] = __float2bfloat16(y.z);
    g_qbf[row][4 * t + 3] = __float2bfloat16(y.w);
}

__global__ void prep_t(const float* __restrict__ txt) {
    int row = blockIdx.x, t = threadIdx.x;
    float4 x;
    float inv = row_sumsq_inv(txt + row * D, x);
    float4 y = make_float4(x.x * inv, x.y * inv, x.z * inv, x.w * inv);
    ((float4*)(g_tf + row * D))[t] = y;
}

__global__ void prep_k(const float* __restrict__ keys) {
    int row = blockIdx.x, t = threadIdx.x;
    float4 x;
    float inv = row_sumsq_inv(keys + row * D, x);
    g_kbf[row][4 * t + 0] = __float2bfloat16(x.x * inv);
    g_kbf[row][4 * t + 1] = __float2bfloat16(x.y * inv);
    g_kbf[row][4 * t + 2] = __float2bfloat16(x.z * inv);
    g_kbf[row][4 * t + 3] = __float2bfloat16(x.w * inv);
}

// ---------------- main kernel: sim = q @ k^T, aff = exp(5 sim), scatter by label ----
extern __shared__ unsigned char smem_raw[];

__global__ void __launch_bounds__(256) gemm_scatter() {
    __nv_bfloat16* As = (__nv_bfloat16*)smem_raw;          // BM*SA
    __nv_bfloat16* Bs = As + BM * SA;                      // BN*SA
    int*   labs = (int*)(Bs + BN * SA);                    // BN
    float* csh  = (float*)(labs + BN);                     // BM*C

    int tid = threadIdx.x;
    int lane = tid & 31, wid = tid >> 5;
    int wm = wid >> 2, wn = wid & 3;   // 2 x 4 warp grid -> warp tile 64x32
    int bt = blockIdx.x;               // b tile 0..7
    int ng = blockIdx.y;               // n group

    for (int i = tid; i < BM * C; i += 256) csh[i] = 0.f;

    const int tiles_per = (NTILES + NGROUPS - 1) / NGROUPS;
    int tS = ng * tiles_per;
    int tE = tS + tiles_per; if (tE > NTILES) tE = NTILES;

    for (int tile = tS; tile < tE; ++tile) {
        __syncthreads();               // previous epilogue done (labs/csh safe)
        if (tid < BN) labs[tid] = g_lab[tile * BN + tid];

        float acc[4][4][4];
#pragma unroll
        for (int mi = 0; mi < 4; mi++)
#pragma unroll
            for (int ni = 0; ni < 4; ni++)
#pragma unroll
                for (int e = 0; e < 4; e++) acc[mi][ni][e] = 0.f;

        int n0 = tile * BN;
        for (int k0 = 0; k0 < D; k0 += BK) {
            __syncthreads();           // previous ldmatrix reads done
#pragma unroll
            for (int i = 0; i < 4; i++) {
                int idx = tid + i * 256;          // 0..1023
                int r = idx >> 3, c = (idx & 7) * 8;
                *(uint4*)(As + r * SA + c) = *(const uint4*)(&g_qbf[bt * BM + r][k0 + c]);
                *(uint4*)(Bs + r * SA + c) = *(const uint4*)(&g_kbf[n0 + r][k0 + c]);
            }
            __syncthreads();

#pragma unroll
            for (int kk = 0; kk < BK; kk += 16) {
                u32 afr[4][4];
#pragma unroll
                for (int mi = 0; mi < 4; mi++) {
                    int rA = wm * 64 + mi * 16 + (lane & 7) + ((lane >> 3) & 1) * 8;
                    int kA = kk + ((lane >> 4) & 1) * 8;
                    ldmx4(afr[mi][0], afr[mi][1], afr[mi][2], afr[mi][3],
                          As + rA * SA + kA);
                }
                u32 bfr[4][2];
#pragma unroll
                for (int g = 0; g < 2; g++) {
                    int nb = wn * 32 + g * 16;
                    int rB = nb + (lane & 7) + ((lane >> 4) & 1) * 8;
                    int kB = kk + ((lane >> 3) & 1) * 8;
                    u32 r0, r1, r2, r3;
                    ldmx4(r0, r1, r2, r3, Bs + rB * SA + kB);
                    bfr[g * 2 + 0][0] = r0; bfr[g * 2 + 0][1] = r1;
                    bfr[g * 2 + 1][0] = r2; bfr[g * 2 + 1][1] = r3;
                }
#pragma unroll
                for (int mi = 0; mi < 4; mi++)
#pragma unroll
                    for (int ni = 0; ni < 4; ni++)
                        mma_bf16(acc[mi][ni], afr[mi], bfr[ni]);
            }
        }

        // epilogue: aff = exp(5 sim), scatter into shared c by label
#pragma unroll
        for (int mi = 0; mi < 4; mi++) {
#pragma unroll
            for (int ni = 0; ni < 4; ni++) {
                int rb = wm * 64 + mi * 16 + (lane >> 2);
                int cb = wn * 32 + ni * 8 + 2 * (lane & 3);
#pragma unroll
                for (int e = 0; e < 4; e++) {
                    int r = rb + ((e >= 2) ? 8 : 0);
                    int c = cb + (e & 1);
                    int n = n0 + c;
                    if (n < NKEYS) {
                        float v = __expf(5.0f * acc[mi][ni][e]);
                        atomicAdd(&csh[r * C + labs[c]], v);
                    }
                }
            }
        }
    }

    __syncthreads();
    for (int i = tid; i < BM * C; i += 256)
        atomicAdd(&g_cacc[bt * BM * C + i], csh[i]);
}

// ---------------- z branch (fp32 GEMM, tiny) + combine ----------------
__global__ void __launch_bounds__(256) zcombine(float* __restrict__ out) {
    __shared__ float a2[64][17];
    __shared__ float b2[64][17];
    int tid = threadIdx.x;
    int tx = tid & 15, ty = tid >> 4;
    int rb = blockIdx.x * 64, cb = blockIdx.y * 64;

    float acc[4][4];
#pragma unroll
    for (int i = 0; i < 4; i++)
#pragma unroll
        for (int j = 0; j < 4; j++) acc[i][j] = 0.f;

    for (int k0 = 0; k0 < D; k0 += 16) {
        __syncthreads();
#pragma unroll
        for (int j = 0; j < 4; j++) {
            int idx = tid + j * 256;       // 0..1023
            int r = idx >> 4, c = idx & 15;
            a2[r][c] = g_qf[(rb + r) * D + k0 + c];
            int cls = cb + r;
            b2[r][c] = (cls < C) ? g_tf[cls * D + k0 + c] : 0.f;
        }
        __syncthreads();
#pragma unroll
        for (int k = 0; k < 16; k++) {
            float av[4], bv[4];
#pragma unroll
            for (int i = 0; i < 4; i++) { av[i] = a2[ty * 4 + i][k]; bv[i] = b2[tx * 4 + i][k]; }
#pragma unroll
            for (int i = 0; i < 4; i++)
#pragma unroll
                for (int j = 0; j < 4; j++) acc[i][j] += av[i] * bv[j];
        }
    }

#pragma unroll
    for (int i = 0; i < 4; i++)
#pragma unroll
        for (int j = 0; j < 4; j++) {
            int r = rb + ty * 4 + i, c = cb + tx * 4 + j;
            if (c < C)
                out[r * C + c] = 50.f * acc[i][j] + 0.5f * g_cacc[r * C + c];
        }
}

// ---------------- launch ----------------
extern "C" void kernel_launch(void* const* d_in, const int* in_sizes, int n_in,
                              void* d_out, int out_size) {
    const float* img  = (const float*)d_in[0];
    const float* txt  = (const float*)d_in[1];
    const float* keys = (const float*)d_in[2];
    const int*   labs = (const int*)d_in[3];   // labels: int32 (JAX x64 disabled)
    float* out = (float*)d_out;

    const int smem_bytes = BM * SA * 2 + BN * SA * 2 + BN * 4 + BM * C * 4;
    cudaFuncSetAttribute(gemm_scatter, cudaFuncAttributeMaxDynamicSharedMemorySize,
                         smem_bytes);

    prep_misc<<<(BDIM * C + 255) / 256, 256>>>(labs);
    prep_q<<<BDIM, 128>>>(img);
    prep_t<<<C, 128>>>(txt);
    prep_k<<<NKEYS, 128>>>(keys);
    gemm_scatter<<<dim3(BTILES, NGROUPS), 256, smem_bytes>>>();
    zcombine<<<dim3(BDIM / 64, 4), 256>>>(out);
}

// round 5
// speedup vs baseline: 1.1083x; 1.1083x over previous
#include <cuda_runtime.h>
#include <cuda_bf16.h>
#include <cstdint>

typedef unsigned int u32;

#define D        512
#define BDIM     1024
#define C        200
#define NKEYS    50000
#define BM       64
#define BN       128
#define BK       64
#define NTILES   391
#define NPAD     (NTILES * BN)
#define BTILES   (BDIM / BM)          // 16
#define NGROUPS  9                    // 16*9 = 144 CTAs = one wave
#define NSTAGES  4
#define SB       72                   // Bs smem stride (bf16), conflict-free
#define SAQ      520                  // As smem stride (bf16), conflict-free
#define CP       201                  // csh padded stride

#define BS_BYTES (BN * SB * 2)                 // 18432
#define OFF_BS   0
#define OFF_AS   (NSTAGES * BS_BYTES)          // 73728
#define OFF_CSH  (OFF_AS + BM * SAQ * 2)       // 140288
#define OFF_LABS (OFF_CSH + BM * CP * 4)       // 191744
#define SMEM_DYN (OFF_LABS + BN * 4)           // 192256

// ---------------- device scratch ----------------
__device__ __align__(16) __nv_bfloat16 g_qbf[BDIM][D];
__device__ float g_qf[BDIM * D];
__device__ float g_tf[C * D];
__device__ __align__(16) __nv_bfloat16 g_kbf[NPAD][D];   // zero-padded tail rows
__device__ int   g_lab[NPAD];
__device__ float g_part[NGROUPS * BDIM * C];             // per-group cache partials

// ---------------- helpers ----------------
__device__ __forceinline__ u32 smem_u32(const void* p) {
    u32 a;
    asm("{ .reg .u64 t; cvta.to.shared.u64 t, %1; cvt.u32.u64 %0, t; }" : "=r"(a) : "l"(p));
    return a;
}

__device__ __forceinline__ void ldmx4(u32& r0, u32& r1, u32& r2, u32& r3, const void* p) {
    u32 addr = smem_u32(p);
    asm volatile("ldmatrix.sync.aligned.m8n8.x4.shared.b16 {%0,%1,%2,%3}, [%4];\n"
                 : "=r"(r0), "=r"(r1), "=r"(r2), "=r"(r3) : "r"(addr));
}

__device__ __forceinline__ void mma_bf16(float* d, const u32* a, const u32* b) {
    asm volatile(
        "mma.sync.aligned.m16n8k16.row.col.f32.bf16.bf16.f32 "
        "{%0,%1,%2,%3}, {%4,%5,%6,%7}, {%8,%9}, {%0,%1,%2,%3};\n"
        : "+f"(d[0]), "+f"(d[1]), "+f"(d[2]), "+f"(d[3])
        : "r"(a[0]), "r"(a[1]), "r"(a[2]), "r"(a[3]), "r"(b[0]), "r"(b[1]));
}

__device__ __forceinline__ void cp16(u32 dst, const void* src) {
    asm volatile("cp.async.cg.shared.global [%0], [%1], 16;" :: "r"(dst), "l"(src));
}
#define CP_COMMIT() asm volatile("cp.async.commit_group;" ::: "memory")
#define CP_WAIT3()  asm volatile("cp.async.wait_group 3;" ::: "memory")

// ---------------- prep kernels ----------------
__global__ void prep_misc(const int* __restrict__ labels) {
    int i = blockIdx.x * blockDim.x + threadIdx.x;
    if (i < NPAD) {
        int l = (i < NKEYS) ? labels[i] : 0;
        l = (l < 0) ? 0 : ((l >= C) ? C - 1 : l);
        g_lab[i] = l;
    }
}

__device__ __forceinline__ float row_sumsq_inv(const float* src, float4& x) {
    int t = threadIdx.x;
    x = ((const float4*)src)[t];
    float ss = x.x * x.x + x.y * x.y + x.z * x.z + x.w * x.w;
#pragma unroll
    for (int o = 16; o; o >>= 1) ss += __shfl_xor_sync(0xffffffffu, ss, o);
    __shared__ float ws[4];
    if ((t & 31) == 0) ws[t >> 5] = ss;
    __syncthreads();
    return rsqrtf(ws[0] + ws[1] + ws[2] + ws[3]);
}

__global__ void prep_q(const float* __restrict__ img) {
    int row = blockIdx.x, t = threadIdx.x;
    float4 x;
    float inv = row_sumsq_inv(img + row * D, x);
    float4 y = make_float4(x.x * inv, x.y * inv, x.z * inv, x.w * inv);
    ((float4*)(g_qf + row * D))[t] = y;
    g_qbf[row][4 * t + 0] = __float2bfloat16(y.x);
    g_qbf[row][4 * t + 1] = __float2bfloat16(y.y);
    g_qbf[row][4 * t + 2] = __float2bfloat16(y.z);
    g_qbf[row][4 * t + 3] = __float2bfloat16(y.w);
}

__global__ void prep_t(const float* __restrict__ txt) {
    int row = blockIdx.x, t = threadIdx.x;
    float4 x;
    float inv = row_sumsq_inv(txt + row * D, x);
    ((float4*)(g_tf + row * D))[t] = make_float4(x.x * inv, x.y * inv, x.z * inv, x.w * inv);
}

__global__ void prep_k(const float* __restrict__ keys) {
    int row = blockIdx.x, t = threadIdx.x;
    float4 x;
    float inv = row_sumsq_inv(keys + row * D, x);
    g_kbf[row][4 * t + 0] = __float2bfloat16(x.x * inv);
    g_kbf[row][4 * t + 1] = __float2bfloat16(x.y * inv);
    g_kbf[row][4 * t + 2] = __float2bfloat16(x.z * inv);
    g_kbf[row][4 * t + 3] = __float2bfloat16(x.w * inv);
}

// ---------------- main kernel: pipelined HMMA GEMM + exp-scatter ----------------
extern __shared__ unsigned char smraw[];

__global__ void __launch_bounds__(256, 1) gemm_scatter() {
    __nv_bfloat16* As = (__nv_bfloat16*)(smraw + OFF_AS);
    float* csh  = (float*)(smraw + OFF_CSH);
    int*   labs = (int*)(smraw + OFF_LABS);

    int tid = threadIdx.x;
    int lane = tid & 31, wid = tid >> 5;
    int wm = wid >> 2, wn = wid & 3;      // 2 x 4 warp grid, warp tile 32x32
    int bt = blockIdx.x;                  // 0..15
    int ng = blockIdx.y;                  // 0..8

    for (int i = tid; i < BM * CP; i += 256) csh[i] = 0.f;

    // group 0: load the whole A panel (64 x 512 bf16) once
    {
        u32 asb = smem_u32(As);
        const char* src = (const char*)&g_qbf[bt * BM][0];
#pragma unroll
        for (int k = 0; k < 16; k++) {
            int idx = tid + k * 256;          // 0..4095
            int r = idx >> 6, c = idx & 63;   // row, 16B chunk
            cp16(asb + (u32)(r * (SAQ * 2) + c * 16), src + r * (D * 2) + c * 16);
        }
        CP_COMMIT();
    }

    int nt = (NTILES - 1 - ng) / NGROUPS + 1;   // strided tiles: ng, ng+9, ...
    int nchunks = nt * 8;
    u32 bsb = smem_u32(smraw + OFF_BS);

    // prologue: key chunks 0..2 (groups 1..3)
    for (int p = 0; p < 3; p++) {
        int tloc = p >> 3, ch = p & 7;
        int n0 = (ng + tloc * NGROUPS) * BN;
        u32 sb = bsb + (u32)(p % NSTAGES) * BS_BYTES;
        const char* src = (const char*)&g_kbf[n0][0] + ch * 128;
#pragma unroll
        for (int k = 0; k < 4; k++) {
            int idx = tid + k * 256;          // 0..1023
            int r = idx >> 3, s = idx & 7;
            cp16(sb + (u32)(r * (SB * 2) + s * 16), src + r * (D * 2) + s * 16);
        }
        CP_COMMIT();
    }

    float acc[2][4][4];
#pragma unroll
    for (int mi = 0; mi < 2; mi++)
#pragma unroll
        for (int ni = 0; ni < 4; ni++)
#pragma unroll
            for (int e = 0; e < 4; e++) acc[mi][ni][e] = 0.f;

    for (int g = 0; g < nchunks; g++) {
        __syncthreads();                      // stage (g+3)%4 free to overwrite
        int pf = g + 3;
        if (pf < nchunks) {
            int tloc = pf >> 3, ch = pf & 7;
            int n0 = (ng + tloc * NGROUPS) * BN;
            u32 sb = bsb + (u32)(pf % NSTAGES) * BS_BYTES;
            const char* src = (const char*)&g_kbf[n0][0] + ch * 128;
#pragma unroll
            for (int k = 0; k < 4; k++) {
                int idx = tid + k * 256;
                int r = idx >> 3, s = idx & 7;
                cp16(sb + (u32)(r * (SB * 2) + s * 16), src + r * (D * 2) + s * 16);
            }
        }
        CP_COMMIT();
        CP_WAIT3();                           // chunk g (and A panel) resident
        __syncthreads();

        int ch = g & 7;
        if (ch == 0 && tid < BN) {
            int n0 = (ng + (g >> 3) * NGROUPS) * BN;
            labs[tid] = g_lab[n0 + tid];
        }

        __nv_bfloat16* Bst = (__nv_bfloat16*)(smraw + OFF_BS + (g % NSTAGES) * BS_BYTES);
#pragma unroll
        for (int ks = 0; ks < 4; ks++) {
            int kk = ks * 16;
            u32 afr[2][4];
#pragma unroll
            for (int mi = 0; mi < 2; mi++) {
                int rA = wm * 32 + mi * 16 + (lane & 7) + ((lane >> 3) & 1) * 8;
                int kA = ch * 64 + kk + ((lane >> 4) & 1) * 8;
                ldmx4(afr[mi][0], afr[mi][1], afr[mi][2], afr[mi][3], As + rA * SAQ + kA);
            }
            u32 bfr[4][2];
#pragma unroll
            for (int gg = 0; gg < 2; gg++) {
                int rB = wn * 32 + gg * 16 + (lane & 7) + ((lane >> 4) & 1) * 8;
                int kB = kk + ((lane >> 3) & 1) * 8;
                u32 r0, r1, r2, r3;
                ldmx4(r0, r1, r2, r3, Bst + rB * SB + kB);
                bfr[gg * 2 + 0][0] = r0; bfr[gg * 2 + 0][1] = r1;
                bfr[gg * 2 + 1][0] = r2; bfr[gg * 2 + 1][1] = r3;
            }
#pragma unroll
            for (int mi = 0; mi < 2; mi++)
#pragma unroll
                for (int ni = 0; ni < 4; ni++)
                    mma_bf16(acc[mi][ni], afr[mi], bfr[ni]);
        }

        if (ch == 7) {                        // tile finished: exp + scatter
            int n0 = (ng + (g >> 3) * NGROUPS) * BN;
#pragma unroll
            for (int mi = 0; mi < 2; mi++) {
#pragma unroll
                for (int ni = 0; ni < 4; ni++) {
                    int rb = wm * 32 + mi * 16 + (lane >> 2);
                    int cb = wn * 32 + ni * 8 + 2 * (lane & 3);
#pragma unroll
                    for (int e = 0; e < 4; e++) {
                        int r = rb + ((e >= 2) ? 8 : 0);
                        int c = cb + (e & 1);
                        if (n0 + c < NKEYS) {
                            float v = __expf(5.0f * acc[mi][ni][e]);
                            atomicAdd(&csh[r * CP + labs[c]], v);
                        }
                        acc[mi][ni][e] = 0.f;
                    }
                }
            }
        }
    }

    __syncthreads();
    float* dst = g_part + ((size_t)ng * BDIM + bt * BM) * C;
    for (int i = tid; i < BM * C; i += 256) {
        int r = i / C, c = i % C;
        dst[i] = csh[r * CP + c];
    }
}

// ---------------- z branch + combine partials ----------------
__global__ void __launch_bounds__(256) zcombine(float* __restrict__ out) {
    __shared__ float a2[64][17];
    __shared__ float b2[64][17];
    int tid = threadIdx.x;
    int tx = tid & 15, ty = tid >> 4;
    int rb = blockIdx.x * 64, cb = blockIdx.y * 64;

    float acc[4][4];
#pragma unroll
    for (int i = 0; i < 4; i++)
#pragma unroll
        for (int j = 0; j < 4; j++) acc[i][j] = 0.f;

    for (int k0 = 0; k0 < D; k0 += 16) {
        __syncthreads();
#pragma unroll
        for (int j = 0; j < 4; j++) {
            int idx = tid + j * 256;
            int r = idx >> 4, c = idx & 15;
            a2[r][c] = g_qf[(rb + r) * D + k0 + c];
            int cls = cb + r;
            b2[r][c] = (cls < C) ? g_tf[cls * D + k0 + c] : 0.f;
        }
        __syncthreads();
#pragma unroll
        for (int k = 0; k < 16; k++) {
            float av[4], bv[4];
#pragma unroll
            for (int i = 0; i < 4; i++) { av[i] = a2[ty * 4 + i][k]; bv[i] = b2[tx * 4 + i][k]; }
#pragma unroll
            for (int i = 0; i < 4; i++)
#pragma unroll
                for (int j = 0; j < 4; j++) acc[i][j] += av[i] * bv[j];
        }
    }

#pragma unroll
    for (int i = 0; i < 4; i++)
#pragma unroll
        for (int j = 0; j < 4; j++) {
            int r = rb + ty * 4 + i, c = cb + tx * 4 + j;
            if (c < C) {
                float s = 0.f;
#pragma unroll
                for (int gg = 0; gg < NGROUPS; gg++)
                    s += g_part[((size_t)gg * BDIM + r) * C + c];
                out[r * C + c] = 50.f * acc[i][j] + 0.5f * s;
            }
        }
}

// ---------------- launch ----------------
extern "C" void kernel_launch(void* const* d_in, const int* in_sizes, int n_in,
                              void* d_out, int out_size) {
    const float* img  = (const float*)d_in[0];
    const float* txt  = (const float*)d_in[1];
    const float* keys = (const float*)d_in[2];
    const int*   labs = (const int*)d_in[3];
    float* out = (float*)d_out;

    cudaFuncSetAttribute(gemm_scatter, cudaFuncAttributeMaxDynamicSharedMemorySize,
                         SMEM_DYN);

    prep_misc<<<(NPAD + 255) / 256, 256>>>(labs);
    prep_q<<<BDIM, 128>>>(img);
    prep_t<<<C, 128>>>(txt);
    prep_k<<<NKEYS, 128>>>(keys);
    gemm_scatter<<<dim3(BTILES, NGROUPS), 256, SMEM_DYN>>>();
    zcombine<<<dim3(BDIM / 64, 4), 256>>>(out);
}